// round 10
// baseline (speedup 1.0000x reference)
#include <cuda_runtime.h>
#include <math.h>

#define LSEQ 2048
#define DMODEL 2048
#define NH 16
#define NKVH 4
#define HDIM 128
#define NE 16
#define NTOPK 4
#define NG 4
#define NTKG 2
#define EI 1024
#define SHI 2048
#define NT 2048
#define EPSV 1e-5f
#define ATTN_SCALE 0.08838834764831845f
#define RSF 2.5f

// smem tile geometry: 128 rows x 32 k-floats, stride 36 (conflict-free)
#define TSTRIDE 36
#define TSTAGE  (128*TSTRIDE)
#define GEMM_SMEM (4*TSTAGE*4)         // 2 stages x (A+B) = 73728 B

typedef unsigned long long ull;

// ---------------- scratch ----------------
__device__ float g_h   [LSEQ*DMODEL];
__device__ float g_q   [LSEQ*NH*HDIM];
__device__ float g_k   [LSEQ*NKVH*HDIM];
__device__ float g_v   [LSEQ*NKVH*HDIM];
__device__ float g_attn[LSEQ*NH*HDIM];
__device__ float g_h1  [LSEQ*DMODEL];
__device__ float g_t   [LSEQ*DMODEL];
__device__ float g_Cw  [NT*NE];
__device__ int   g_cnt [NE];
__device__ int   g_bucket[NE*NT];
__device__ float g_eg  [(size_t)NE*NT*EI];
__device__ float g_eu  [(size_t)NE*NT*EI];
__device__ float g_sg  [(size_t)NT*SHI];
__device__ float g_su  [(size_t)NT*SHI];
__device__ float g_y   [(size_t)NT*DMODEL];
__device__ float g_cos [LSEQ*64];
__device__ float g_sin [LSEQ*64];

// ---------------- helpers ----------------
__device__ __forceinline__ unsigned f2tf(float f){
    unsigned u; asm("cvt.rna.tf32.f32 %0,%1;" : "=r"(u) : "f"(f)); return u;
}
__device__ __forceinline__ void mma_tf32(float c[4],
    unsigned a0, unsigned a1, unsigned a2, unsigned a3, unsigned b0, unsigned b1)
{
    asm volatile("mma.sync.aligned.m16n8k8.row.col.f32.tf32.tf32.f32 "
        "{%0,%1,%2,%3},{%4,%5,%6,%7},{%8,%9},{%0,%1,%2,%3};"
        : "+f"(c[0]), "+f"(c[1]), "+f"(c[2]), "+f"(c[3])
        : "r"(a0), "r"(a1), "r"(a2), "r"(a3), "r"(b0), "r"(b1));
}
__device__ __forceinline__ unsigned sptr(const void* p){
    return (unsigned)__cvta_generic_to_shared(p);
}
__device__ __forceinline__ void ldsm4(unsigned &r0, unsigned &r1, unsigned &r2, unsigned &r3,
                                      unsigned addr)
{
    asm volatile("ldmatrix.sync.aligned.m8n8.x4.shared.b16 {%0,%1,%2,%3}, [%4];"
        : "=r"(r0), "=r"(r1), "=r"(r2), "=r"(r3) : "r"(addr));
}
#define CPA16(dst, src, n) asm volatile( \
    "cp.async.cg.shared.global [%0], [%1], 16, %2;\n" :: "r"(dst), "l"(src), "r"(n))
#define CPCOMMIT() asm volatile("cp.async.commit_group;\n" ::: "memory")
#define CPWAIT0()  asm volatile("cp.async.wait_group 0;\n" ::: "memory")

// f32x2 packed math
__device__ __forceinline__ ull pack2(float lo, float hi){
    ull r; asm("mov.b64 %0,{%1,%2};" : "=l"(r) : "f"(lo), "f"(hi)); return r;
}
__device__ __forceinline__ void unpack2(ull v, float &lo, float &hi){
    asm("mov.b64 {%0,%1},%2;" : "=f"(lo), "=f"(hi) : "l"(v));
}
__device__ __forceinline__ ull fma2(ull a, ull b, ull c){
    ull d; asm("fma.rn.f32x2 %0,%1,%2,%3;" : "=l"(d) : "l"(a), "l"(b), "l"(c)); return d;
}
__device__ __forceinline__ ull mul2(ull a, ull b){
    ull d; asm("mul.rn.f32x2 %0,%1,%2;" : "=l"(d) : "l"(a), "l"(b)); return d;
}

// ---------------- fragment lane offsets (bytes within a stage) ----------------
// A matrices (per mt, ldmatrix.x4): m0 = rows +0..7 colblk ks, m1 = rows +8..15 colblk ks,
// m2 = rows +0..7 colblk ks+4, m3 = rows +8..15 colblk ks+4  -> frags {a0,a1,a2,a3}
// B pair p covers nt=2p,2p+1: m0=(2p, cb0) m1=(2p, cb4) m2=(2p+1, cb0) m3=(2p+1, cb4)
__device__ __forceinline__ void frag_offsets(int lane, int wm, int wn,
                                             unsigned* aOff, unsigned* bOff)
{
    int g = lane >> 3, lr = lane & 7;
    #pragma unroll
    for (int mt = 0; mt < 4; mt++)
        aOff[mt] = ((wm + mt*16 + (g & 1)*8 + lr) * TSTRIDE + (g >> 1)*4) * 4;
    #pragma unroll
    for (int p = 0; p < 2; p++)
        bOff[p] = ((wn + (2*p + (g >> 1))*8 + lr) * TSTRIDE + (g & 1)*4) * 4;
}

// ---------------- MMA stage compute via ldmatrix ----------------
__device__ __forceinline__ void mma_ldsm_1x(unsigned baseA, unsigned baseB,
    const unsigned* aOff, const unsigned* bOff, float (*acc)[4][4])
{
    #pragma unroll
    for (int ks = 0; ks < 32; ks += 8) {
        unsigned a[4][4], b[2][4];
        #pragma unroll
        for (int mt = 0; mt < 4; mt++)
            ldsm4(a[mt][0], a[mt][1], a[mt][2], a[mt][3], baseA + aOff[mt] + ks*4);
        #pragma unroll
        for (int p = 0; p < 2; p++)
            ldsm4(b[p][0], b[p][1], b[p][2], b[p][3], baseB + bOff[p] + ks*4);
        unsigned aT[4][4], bT[4][2];
        #pragma unroll
        for (int mt = 0; mt < 4; mt++)
            #pragma unroll
            for (int i = 0; i < 4; i++)
                aT[mt][i] = f2tf(__uint_as_float(a[mt][i]));
        #pragma unroll
        for (int p = 0; p < 2; p++) {
            bT[2*p][0]   = f2tf(__uint_as_float(b[p][0]));
            bT[2*p][1]   = f2tf(__uint_as_float(b[p][1]));
            bT[2*p+1][0] = f2tf(__uint_as_float(b[p][2]));
            bT[2*p+1][1] = f2tf(__uint_as_float(b[p][3]));
        }
        #pragma unroll
        for (int mt = 0; mt < 4; mt++)
            #pragma unroll
            for (int nt = 0; nt < 4; nt++)
                mma_tf32(acc[mt][nt], aT[mt][0], aT[mt][1], aT[mt][2], aT[mt][3],
                         bT[nt][0], bT[nt][1]);
    }
}

__device__ __forceinline__ void mma_ldsm_3x(unsigned baseA, unsigned baseB,
    const unsigned* aOff, const unsigned* bOff, float (*acc)[4][4])
{
    #pragma unroll
    for (int ks = 0; ks < 32; ks += 8) {
        unsigned a[4][4], b[2][4];
        #pragma unroll
        for (int mt = 0; mt < 4; mt++)
            ldsm4(a[mt][0], a[mt][1], a[mt][2], a[mt][3], baseA + aOff[mt] + ks*4);
        #pragma unroll
        for (int p = 0; p < 2; p++)
            ldsm4(b[p][0], b[p][1], b[p][2], b[p][3], baseB + bOff[p] + ks*4);
        unsigned aH[4][4], aL[4][4], bH[4][2], bL[4][2];
        #pragma unroll
        for (int mt = 0; mt < 4; mt++)
            #pragma unroll
            for (int i = 0; i < 4; i++) {
                float v = __uint_as_float(a[mt][i]);
                aH[mt][i] = f2tf(v);
                aL[mt][i] = f2tf(v - __uint_as_float(aH[mt][i]));
            }
        #pragma unroll
        for (int p = 0; p < 2; p++) {
            #pragma unroll
            for (int i = 0; i < 4; i++) {
                float v = __uint_as_float(b[p][i]);
                unsigned h = f2tf(v);
                unsigned l = f2tf(v - __uint_as_float(h));
                int nt = 2*p + (i >> 1), cc = i & 1;
                bH[nt][cc] = h; bL[nt][cc] = l;
            }
        }
        #pragma unroll
        for (int mt = 0; mt < 4; mt++)
            #pragma unroll
            for (int nt = 0; nt < 4; nt++) {
                mma_tf32(acc[mt][nt], aH[mt][0], aH[mt][1], aH[mt][2], aH[mt][3], bH[nt][0], bH[nt][1]);
                mma_tf32(acc[mt][nt], aL[mt][0], aL[mt][1], aL[mt][2], aL[mt][3], bH[nt][0], bH[nt][1]);
                mma_tf32(acc[mt][nt], aH[mt][0], aH[mt][1], aH[mt][2], aH[mt][3], bL[nt][0], bL[nt][1]);
            }
    }
}

// ============ fused QKV projection (3xTF32, pipelined, ldmatrix) ============
__global__ __launch_bounds__(256, 2) void qkv3_kernel(const float* __restrict__ A,
    const float* __restrict__ wq, const float* __restrict__ wk, const float* __restrict__ wv)
{
    extern __shared__ float sm[];
    float* As = sm;
    float* Bs = sm + 2*TSTAGE;
    const int K = DMODEL;
    int tid = threadIdx.x, lane = tid & 31, warp = tid >> 5;
    int m0 = blockIdx.y * 128, n0 = blockIdx.x * 128;
    int wm = (warp & 1) * 64, wn = (warp >> 1) * 32;

    const float* B; float* Cp; int ldc, ncol0;
    if (n0 < 2048)      { B = wq + (size_t)n0 * K;          Cp = g_q; ldc = NH*HDIM;   ncol0 = n0; }
    else if (n0 < 2560) { B = wk + (size_t)(n0 - 2048) * K; Cp = g_k; ldc = NKVH*HDIM; ncol0 = n0 - 2048; }
    else                { B = wv + (size_t)(n0 - 2560) * K; Cp = g_v; ldc = NKVH*HDIM; ncol0 = n0 - 2560; }

    unsigned aOff[4], bOff[2];
    frag_offsets(lane, wm, wn, aOff, bOff);
    unsigned sA[2] = { sptr(As), sptr(As + TSTAGE) };
    unsigned sB[2] = { sptr(Bs), sptr(Bs + TSTAGE) };

    const float* aSrc[4]; const float* bSrc[4]; int soff[4];
    #pragma unroll
    for (int i = 0; i < 4; i++) {
        int idx = tid + i * 256, row = idx >> 3, ch = idx & 7;
        soff[i] = row * TSTRIDE + ch * 4;
        aSrc[i] = A + (size_t)(m0 + row) * K + ch * 4;
        bSrc[i] = B + (size_t)row * K + ch * 4;
    }
    #pragma unroll
    for (int i = 0; i < 4; i++) {
        CPA16(sptr(As + soff[i]), aSrc[i], 16);
        CPA16(sptr(Bs + soff[i]), bSrc[i], 16);
    }
    CPCOMMIT();

    float acc[4][4][4] = {};
    for (int k0 = 0; k0 < K; k0 += 32) {
        CPWAIT0(); __syncthreads();
        int cur = (k0 >> 5) & 1, nxt = cur ^ 1;
        if (k0 + 32 < K) {
            #pragma unroll
            for (int i = 0; i < 4; i++) {
                CPA16(sptr(As + nxt*TSTAGE + soff[i]), aSrc[i] + k0 + 32, 16);
                CPA16(sptr(Bs + nxt*TSTAGE + soff[i]), bSrc[i] + k0 + 32, 16);
            }
            CPCOMMIT();
        }
        mma_ldsm_3x(sA[cur], sB[cur], aOff, bOff, acc);
    }
    int r = lane >> 2, c2 = (lane & 3) * 2;
    #pragma unroll
    for (int mt = 0; mt < 4; mt++) {
        int mrow = m0 + wm + mt * 16 + r;
        #pragma unroll
        for (int nt = 0; nt < 4; nt++) {
            int col = ncol0 + wn + nt * 8 + c2;
            size_t i00 = (size_t)mrow * ldc + col;
            size_t i10 = (size_t)(mrow + 8) * ldc + col;
            Cp[i00] = acc[mt][nt][0]; Cp[i00+1] = acc[mt][nt][1];
            Cp[i10] = acc[mt][nt][2]; Cp[i10+1] = acc[mt][nt][3];
        }
    }
}

// ============ o-proj + residual (3xTF32, pipelined, ldmatrix) ============
__global__ __launch_bounds__(256, 2) void gemm3o_kernel(const float* __restrict__ A,
    const float* __restrict__ B, float* __restrict__ C, const float* __restrict__ R)
{
    extern __shared__ float sm[];
    float* As = sm;
    float* Bs = sm + 2*TSTAGE;
    const int K = NH*HDIM, N = DMODEL;
    int tid = threadIdx.x, lane = tid & 31, warp = tid >> 5;
    int m0 = blockIdx.y * 128, n0 = blockIdx.x * 128;
    int wm = (warp & 1) * 64, wn = (warp >> 1) * 32;

    unsigned aOff[4], bOff[2];
    frag_offsets(lane, wm, wn, aOff, bOff);
    unsigned sA[2] = { sptr(As), sptr(As + TSTAGE) };
    unsigned sB[2] = { sptr(Bs), sptr(Bs + TSTAGE) };

    const float* aSrc[4]; const float* bSrc[4]; int soff[4];
    #pragma unroll
    for (int i = 0; i < 4; i++) {
        int idx = tid + i * 256, row = idx >> 3, ch = idx & 7;
        soff[i] = row * TSTRIDE + ch * 4;
        aSrc[i] = A + (size_t)(m0 + row) * K + ch * 4;
        bSrc[i] = B + (size_t)(n0 + row) * K + ch * 4;
    }
    #pragma unroll
    for (int i = 0; i < 4; i++) {
        CPA16(sptr(As + soff[i]), aSrc[i], 16);
        CPA16(sptr(Bs + soff[i]), bSrc[i], 16);
    }
    CPCOMMIT();

    float acc[4][4][4] = {};
    for (int k0 = 0; k0 < K; k0 += 32) {
        CPWAIT0(); __syncthreads();
        int cur = (k0 >> 5) & 1, nxt = cur ^ 1;
        if (k0 + 32 < K) {
            #pragma unroll
            for (int i = 0; i < 4; i++) {
                CPA16(sptr(As + nxt*TSTAGE + soff[i]), aSrc[i] + k0 + 32, 16);
                CPA16(sptr(Bs + nxt*TSTAGE + soff[i]), bSrc[i] + k0 + 32, 16);
            }
            CPCOMMIT();
        }
        mma_ldsm_3x(sA[cur], sB[cur], aOff, bOff, acc);
    }
    int r = lane >> 2, c2 = (lane & 3) * 2;
    #pragma unroll
    for (int mt = 0; mt < 4; mt++) {
        int mrow = m0 + wm + mt * 16 + r;
        #pragma unroll
        for (int nt = 0; nt < 4; nt++) {
            int col = n0 + wn + nt * 8 + c2;
            size_t i00 = (size_t)mrow * N + col;
            size_t i10 = (size_t)(mrow + 8) * N + col;
            C[i00] = acc[mt][nt][0] + R[i00]; C[i00+1] = acc[mt][nt][1] + R[i00+1];
            C[i10] = acc[mt][nt][2] + R[i10]; C[i10+1] = acc[mt][nt][3] + R[i10+1];
        }
    }
}

// ============ dual dense 1xTF32 GEMM (z selects gate/up) ============
__global__ __launch_bounds__(256, 2) void dense1_dual_kernel(const float* __restrict__ A,
    const float* __restrict__ B0, const float* __restrict__ B1,
    float* __restrict__ C0, float* __restrict__ C1, int N, int K)
{
    const float* Bsel = blockIdx.z ? B1 : B0;
    float* Csel = blockIdx.z ? C1 : C0;
    extern __shared__ float sm[];
    float* As = sm;
    float* Bs = sm + 2*TSTAGE;
    int tid = threadIdx.x, lane = tid & 31, warp = tid >> 5;
    int m0 = blockIdx.y * 128, n0 = blockIdx.x * 128;
    int wm = (warp & 1) * 64, wn = (warp >> 1) * 32;

    unsigned aOff[4], bOff[2];
    frag_offsets(lane, wm, wn, aOff, bOff);
    unsigned sA[2] = { sptr(As), sptr(As + TSTAGE) };
    unsigned sB[2] = { sptr(Bs), sptr(Bs + TSTAGE) };

    const float* aSrc[4]; const float* bSrc[4]; int soff[4];
    #pragma unroll
    for (int i = 0; i < 4; i++) {
        int idx = tid + i * 256, row = idx >> 3, ch = idx & 7;
        soff[i] = row * TSTRIDE + ch * 4;
        aSrc[i] = A + (size_t)(m0 + row) * K + ch * 4;
        bSrc[i] = Bsel + (size_t)(n0 + row) * K + ch * 4;
    }
    #pragma unroll
    for (int i = 0; i < 4; i++) {
        CPA16(sptr(As + soff[i]), aSrc[i], 16);
        CPA16(sptr(Bs + soff[i]), bSrc[i], 16);
    }
    CPCOMMIT();

    float acc[4][4][4] = {};
    for (int k0 = 0; k0 < K; k0 += 32) {
        CPWAIT0(); __syncthreads();
        int cur = (k0 >> 5) & 1, nxt = cur ^ 1;
        if (k0 + 32 < K) {
            #pragma unroll
            for (int i = 0; i < 4; i++) {
                CPA16(sptr(As + nxt*TSTAGE + soff[i]), aSrc[i] + k0 + 32, 16);
                CPA16(sptr(Bs + nxt*TSTAGE + soff[i]), bSrc[i] + k0 + 32, 16);
            }
            CPCOMMIT();
        }
        mma_ldsm_1x(sA[cur], sB[cur], aOff, bOff, acc);
    }
    int r = lane >> 2, c2 = (lane & 3) * 2;
    #pragma unroll
    for (int mt = 0; mt < 4; mt++) {
        int mrow = m0 + wm + mt * 16 + r;
        #pragma unroll
        for (int nt = 0; nt < 4; nt++) {
            int col = n0 + wn + nt * 8 + c2;
            size_t i00 = (size_t)mrow * N + col;
            size_t i10 = (size_t)(mrow + 8) * N + col;
            Csel[i00] = acc[mt][nt][0]; Csel[i00+1] = acc[mt][nt][1];
            Csel[i10] = acc[mt][nt][2]; Csel[i10+1] = acc[mt][nt][3];
        }
    }
}

// ============ dense 1xTF32 GEMM ============
__global__ __launch_bounds__(256, 2) void dense1_kernel(const float* __restrict__ A,
    const float* __restrict__ B, float* __restrict__ C, int N, int K)
{
    extern __shared__ float sm[];
    float* As = sm;
    float* Bs = sm + 2*TSTAGE;
    int tid = threadIdx.x, lane = tid & 31, warp = tid >> 5;
    int m0 = blockIdx.y * 128, n0 = blockIdx.x * 128;
    int wm = (warp & 1) * 64, wn = (warp >> 1) * 32;

    unsigned aOff[4], bOff[2];
    frag_offsets(lane, wm, wn, aOff, bOff);
    unsigned sA[2] = { sptr(As), sptr(As + TSTAGE) };
    unsigned sB[2] = { sptr(Bs), sptr(Bs + TSTAGE) };

    const float* aSrc[4]; const float* bSrc[4]; int soff[4];
    #pragma unroll
    for (int i = 0; i < 4; i++) {
        int idx = tid + i * 256, row = idx >> 3, ch = idx & 7;
        soff[i] = row * TSTRIDE + ch * 4;
        aSrc[i] = A + (size_t)(m0 + row) * K + ch * 4;
        bSrc[i] = B + (size_t)(n0 + row) * K + ch * 4;
    }
    #pragma unroll
    for (int i = 0; i < 4; i++) {
        CPA16(sptr(As + soff[i]), aSrc[i], 16);
        CPA16(sptr(Bs + soff[i]), bSrc[i], 16);
    }
    CPCOMMIT();

    float acc[4][4][4] = {};
    for (int k0 = 0; k0 < K; k0 += 32) {
        CPWAIT0(); __syncthreads();
        int cur = (k0 >> 5) & 1, nxt = cur ^ 1;
        if (k0 + 32 < K) {
            #pragma unroll
            for (int i = 0; i < 4; i++) {
                CPA16(sptr(As + nxt*TSTAGE + soff[i]), aSrc[i] + k0 + 32, 16);
                CPA16(sptr(Bs + nxt*TSTAGE + soff[i]), bSrc[i] + k0 + 32, 16);
            }
            CPCOMMIT();
        }
        mma_ldsm_1x(sA[cur], sB[cur], aOff, bOff, acc);
    }
    int r = lane >> 2, c2 = (lane & 3) * 2;
    #pragma unroll
    for (int mt = 0; mt < 4; mt++) {
        int mrow = m0 + wm + mt * 16 + r;
        #pragma unroll
        for (int nt = 0; nt < 4; nt++) {
            int col = n0 + wn + nt * 8 + c2;
            size_t i00 = (size_t)mrow * N + col;
            size_t i10 = (size_t)(mrow + 8) * N + col;
            C[i00] = acc[mt][nt][0]; C[i00+1] = acc[mt][nt][1];
            C[i10] = acc[mt][nt][2]; C[i10+1] = acc[mt][nt][3];
        }
    }
}

// ============ gathered expert gate+up GEMM (1xTF32), z = e*2 + which ============
__global__ __launch_bounds__(256, 2) void egu1_kernel(const float* __restrict__ wg,
    const float* __restrict__ wu)
{
    int e = blockIdx.z >> 1;
    int which = blockIdx.z & 1;
    int cnt = g_cnt[e];
    int m0 = blockIdx.y * 128;
    if (m0 >= cnt) return;
    int n0 = blockIdx.x * 128;
    const float* W = which ? wu : wg;
    float* Cout = which ? g_eu : g_eg;
    extern __shared__ float sm[];
    float* As = sm;
    float* Bs = sm + 2*TSTAGE;
    __shared__ int toks[128];
    const int K = DMODEL;
    int tid = threadIdx.x, lane = tid & 31, warp = tid >> 5;
    if (tid < 128) {
        int m = m0 + tid;
        toks[tid] = (m < cnt) ? g_bucket[e * NT + m] : -1;
    }
    __syncthreads();
    const float* B = W + (size_t)e * EI * DMODEL + (size_t)n0 * K;
    int wm = (warp & 1) * 64, wn = (warp >> 1) * 32;

    unsigned aOff[4], bOff[2];
    frag_offsets(lane, wm, wn, aOff, bOff);
    unsigned sA[2] = { sptr(As), sptr(As + TSTAGE) };
    unsigned sB[2] = { sptr(Bs), sptr(Bs + TSTAGE) };

    const float* aSrc[4]; const float* bSrc[4]; int soff[4]; int aBytes[4];
    #pragma unroll
    for (int i = 0; i < 4; i++) {
        int idx = tid + i * 256, row = idx >> 3, ch = idx & 7;
        soff[i] = row * TSTRIDE + ch * 4;
        int tok = toks[row];
        aBytes[i] = (tok >= 0) ? 16 : 0;
        aSrc[i] = g_t + (size_t)(tok >= 0 ? tok : 0) * K + ch * 4;
        bSrc[i] = B + (size_t)row * K + ch * 4;
    }
    #pragma unroll
    for (int i = 0; i < 4; i++) {
        CPA16(sptr(As + soff[i]), aSrc[i], aBytes[i]);
        CPA16(sptr(Bs + soff[i]), bSrc[i], 16);
    }
    CPCOMMIT();

    float acc[4][4][4] = {};
    for (int k0 = 0; k0 < K; k0 += 32) {
        CPWAIT0(); __syncthreads();
        int cur = (k0 >> 5) & 1, nxt = cur ^ 1;
        if (k0 + 32 < K) {
            #pragma unroll
            for (int i = 0; i < 4; i++) {
                CPA16(sptr(As + nxt*TSTAGE + soff[i]), aSrc[i] + k0 + 32, aBytes[i]);
                CPA16(sptr(Bs + nxt*TSTAGE + soff[i]), bSrc[i] + k0 + 32, 16);
            }
            CPCOMMIT();
        }
        mma_ldsm_1x(sA[cur], sB[cur], aOff, bOff, acc);
    }
    int r = lane >> 2, c2 = (lane & 3) * 2;
    #pragma unroll
    for (int mt = 0; mt < 4; mt++) {
        int mloc = wm + mt * 16 + r;
        int m = m0 + mloc;
        #pragma unroll
        for (int nt = 0; nt < 4; nt++) {
            int col = n0 + wn + nt * 8 + c2;
            if (m < cnt) {
                size_t i00 = ((size_t)e * NT + m) * EI + col;
                Cout[i00] = acc[mt][nt][0]; Cout[i00+1] = acc[mt][nt][1];
            }
            if (m + 8 < cnt) {
                size_t i10 = ((size_t)e * NT + m + 8) * EI + col;
                Cout[i10] = acc[mt][nt][2]; Cout[i10+1] = acc[mt][nt][3];
            }
        }
    }
}

// ============ expert down GEMM (1xTF32) + scatter atomicAdd ============
__global__ __launch_bounds__(256, 2) void edown1_kernel(const float* __restrict__ wd)
{
    int e = blockIdx.z;
    int cnt = g_cnt[e];
    int m0 = blockIdx.y * 128;
    if (m0 >= cnt) return;
    int n0 = blockIdx.x * 128;
    extern __shared__ float sm[];
    float* As = sm;
    float* Bs = sm + 2*TSTAGE;
    __shared__ int toks[128];
    const int K = EI;
    int tid = threadIdx.x, lane = tid & 31, warp = tid >> 5;
    if (tid < 128) {
        int m = m0 + tid;
        toks[tid] = (m < cnt) ? g_bucket[e * NT + m] : -1;
    }
    __syncthreads();
    const float* Ae = g_eg + ((size_t)e * NT + m0) * EI;
    const float* B = wd + (size_t)e * DMODEL * EI + (size_t)n0 * K;
    int wm = (warp & 1) * 64, wn = (warp >> 1) * 32;

    unsigned aOff[4], bOff[2];
    frag_offsets(lane, wm, wn, aOff, bOff);
    unsigned sA[2] = { sptr(As), sptr(As + TSTAGE) };
    unsigned sB[2] = { sptr(Bs), sptr(Bs + TSTAGE) };

    const float* aSrc[4]; const float* bSrc[4]; int soff[4]; int aBytes[4];
    #pragma unroll
    for (int i = 0; i < 4; i++) {
        int idx = tid + i * 256, row = idx >> 3, ch = idx & 7;
        soff[i] = row * TSTRIDE + ch * 4;
        bool ok = (m0 + row) < cnt;
        aBytes[i] = ok ? 16 : 0;
        aSrc[i] = Ae + (size_t)(ok ? row : 0) * K + ch * 4;
        bSrc[i] = B + (size_t)row * K + ch * 4;
    }
    #pragma unroll
    for (int i = 0; i < 4; i++) {
        CPA16(sptr(As + soff[i]), aSrc[i], aBytes[i]);
        CPA16(sptr(Bs + soff[i]), bSrc[i], 16);
    }
    CPCOMMIT();

    float acc[4][4][4] = {};
    for (int k0 = 0; k0 < K; k0 += 32) {
        CPWAIT0(); __syncthreads();
        int cur = (k0 >> 5) & 1, nxt = cur ^ 1;
        if (k0 + 32 < K) {
            #pragma unroll
            for (int i = 0; i < 4; i++) {
                CPA16(sptr(As + nxt*TSTAGE + soff[i]), aSrc[i] + k0 + 32, aBytes[i]);
                CPA16(sptr(Bs + nxt*TSTAGE + soff[i]), bSrc[i] + k0 + 32, 16);
            }
            CPCOMMIT();
        }
        mma_ldsm_1x(sA[cur], sB[cur], aOff, bOff, acc);
    }
    int r = lane >> 2, c2 = (lane & 3) * 2;
    #pragma unroll
    for (int mt = 0; mt < 4; mt++) {
        int mloc = wm + mt * 16 + r;
        #pragma unroll
        for (int nt = 0; nt < 4; nt++) {
            int col = n0 + wn + nt * 8 + c2;
            if (m0 + mloc < cnt) {
                int tok = toks[mloc];
                atomicAdd(&g_y[(size_t)tok * DMODEL + col],     acc[mt][nt][0]);
                atomicAdd(&g_y[(size_t)tok * DMODEL + col + 1], acc[mt][nt][1]);
            }
            if (m0 + mloc + 8 < cnt) {
                int tok = toks[mloc + 8];
                atomicAdd(&g_y[(size_t)tok * DMODEL + col],     acc[mt][nt][2]);
                atomicAdd(&g_y[(size_t)tok * DMODEL + col + 1], acc[mt][nt][3]);
            }
        }
    }
}

// ---------------- RoPE table (double-precision trig, fast-math-immune) ----------------
__global__ void rope_table_kernel()
{
    int pos = blockIdx.x, j = threadIdx.x;
    float p    = (float)pow(1000000.0, (double)j / 64.0);
    float freq = 1.0f / p;
    float ang  = (float)pos * freq;
    double sd, cd; sincos((double)ang, &sd, &cd);
    g_cos[pos * 64 + j] = (float)cd;
    g_sin[pos * 64 + j] = (float)sd;
}

// ---------------- RMSNorm ----------------
__global__ __launch_bounds__(256) void rmsnorm_kernel(const float* __restrict__ x,
                                                      const float* __restrict__ w,
                                                      float* __restrict__ out)
{
    int row = blockIdx.x;
    const float* xr = x + (size_t)row * DMODEL;
    float ss = 0.f;
    for (int d = threadIdx.x; d < DMODEL; d += 256) { float v = xr[d]; ss += v * v; }
    __shared__ float red[8];
    #pragma unroll
    for (int off = 16; off; off >>= 1) ss += __shfl_xor_sync(0xffffffffu, ss, off);
    if ((threadIdx.x & 31) == 0) red[threadIdx.x >> 5] = ss;
    __syncthreads();
    __shared__ float sinv;
    if (threadIdx.x == 0) {
        float tot = 0.f;
        #pragma unroll
        for (int i = 0; i < 8; i++) tot += red[i];
        sinv = 1.f / sqrtf(tot / (float)DMODEL + EPSV);
    }
    __syncthreads();
    float si = sinv;
    for (int d = threadIdx.x; d < DMODEL; d += 256)
        out[(size_t)row * DMODEL + d] = xr[d] * si * w[d];
}

// ---------------- fused per-(token,head) RMSNorm + RoPE (q and k in one grid) ----------------
__global__ __launch_bounds__(128) void qknorm_rope_kernel(const float* __restrict__ qw,
                                                          const float* __restrict__ kw)
{
    int row = blockIdx.x;
    float* buf; const float* w; int nh;
    if (row < LSEQ * NH) { buf = g_q; w = qw; nh = NH; }
    else { row -= LSEQ * NH; buf = g_k; w = kw; nh = NKVH; }
    int pos = row / nh;
    float* p = buf + (size_t)row * HDIM;
    int tid = threadIdx.x;
    float v = p[tid];
    float ss = v * v;
    #pragma unroll
    for (int off = 16; off; off >>= 1) ss += __shfl_xor_sync(0xffffffffu, ss, off);
    __shared__ float red[4];
    if ((tid & 31) == 0) red[tid >> 5] = ss;
    __syncthreads();
    __shared__ float sinv;
    if (tid == 0) sinv = 1.f / sqrtf((red[0] + red[1] + red[2] + red[3]) / (float)HDIM + EPSV);
    __shared__ float shn[HDIM];
    __syncthreads();
    shn[tid] = v * sinv * w[tid];
    __syncthreads();
    if (tid < 64) {
        float x1 = shn[tid], x2 = shn[tid + 64];
        float c = g_cos[pos * 64 + tid], s = g_sin[pos * 64 + tid];
        p[tid]      = x1 * c - x2 * s;
        p[tid + 64] = x2 * c + x1 * s;
    }
}

// ---------------- flash attention (fp32 via f32x2, causal, GQA) ----------------
__global__ __launch_bounds__(128) void attn_kernel()
{
    __shared__ __align__(16) float Qs[32][HDIM];
    __shared__ __align__(16) float Ks[32][HDIM];
    __shared__ __align__(16) float Vs[32][HDIM];
    int h = blockIdx.y;
    int q0 = blockIdx.x * 32;
    int kvh = h >> 2;
    int tid = threadIdx.x;
    int r = tid >> 2, qd = tid & 3;

    for (int i = tid; i < 32 * 32; i += 128) {
        int row = i >> 5, d4 = i & 31;
        ((float4*)&Qs[row][0])[d4] =
            *(const float4*)(g_q + (size_t)(q0 + row) * (NH * HDIM) + h * HDIM + d4 * 4);
    }
    __syncthreads();
    ull qq[16];
    #pragma unroll
    for (int i = 0; i < 16; i++) qq[i] = *(const ull*)&Qs[r][qd * 32 + i * 2];

    ull o2[16];
    #pragma unroll
    for (int i = 0; i < 16; i++) o2[i] = 0ULL;
    float mrow = -INFINITY, lrow = 0.f;

    for (int k0 = 0; k0 <= q0; k0 += 32) {
        __syncthreads();
        for (int i = tid; i < 32 * 32; i += 128) {
            int row = i >> 5, d4 = i & 31;
            size_t base = (size_t)(k0 + row) * (NKVH * HDIM) + kvh * HDIM + d4 * 4;
            ((float4*)&Ks[row][0])[d4] = *(const float4*)(g_k + base);
            ((float4*)&Vs[row][0])[d4] = *(const float4*)(g_v + base);
        }
        __syncthreads();

        float s[32];
        float tmax = -INFINITY;
        #pragma unroll
        for (int j = 0; j < 32; j++) {
            const ull* K2 = (const ull*)&Ks[j][qd * 32];
            ull acc2 = 0ULL;
            #pragma unroll
            for (int i = 0; i < 16; i++) acc2 = fma2(qq[i], K2[i], acc2);
            float elo, ehi; unpack2(acc2, elo, ehi);
            float pacc = elo + ehi;
            pacc += __shfl_xor_sync(0xffffffffu, pacc, 1);
            pacc += __shfl_xor_sync(0xffffffffu, pacc, 2);
            pacc *= ATTN_SCALE;
            if (k0 + j > q0 + r) pacc = -INFINITY;
            s[j] = pacc;
            tmax = fmaxf(tmax, pacc);
        }
        float mnew = fmaxf(mrow, tmax);
        float alpha = __expf(mrow - mnew);
        lrow *= alpha;
        ull al2 = pack2(alpha, alpha);
        #pragma unroll
        for (int i = 0; i < 16; i++) o2[i] = mul2(o2[i], al2);
        #pragma unroll
        for (int j = 0; j < 32; j++) {
            float pv = __expf(s[j] - mnew);
            lrow += pv;
            ull pv2 = pack2(pv, pv);
            const ull* V2 = (const ull*)&Vs[j][qd * 32];
            #pragma unroll
            for (int i = 0; i < 16; i++) o2[i] = fma2(pv2, V2[i], o2[i]);
        }
        mrow = mnew;
    }
    float inv = 1.f / lrow;
    size_t base = (size_t)(q0 + r) * (NH * HDIM) + h * HDIM + qd * 32;
    #pragma unroll
    for (int i = 0; i < 16; i++) {
        float lo, hi; unpack2(o2[i], lo, hi);
        g_attn[base + i * 2]     = lo * inv;
        g_attn[base + i * 2 + 1] = hi * inv;
    }
}

// ---------------- zero expert counters ----------------
__global__ void zero_cnt_kernel()
{
    if (threadIdx.x < NE) g_cnt[threadIdx.x] = 0;
}

// ---------------- gating / routing (fp32, exact) ----------------
__global__ __launch_bounds__(256) void gate_kernel(const float* __restrict__ gate_w,
                                                   const float* __restrict__ gate_bias)
{
    int t = blockIdx.x;
    const float* tr = g_t + (size_t)t * DMODEL;
    float acc[NE];
    #pragma unroll
    for (int e = 0; e < NE; e++) acc[e] = 0.f;
    for (int d = threadIdx.x; d < DMODEL; d += 256) {
        float xv = tr[d];
        #pragma unroll
        for (int e = 0; e < NE; e++) acc[e] += xv * gate_w[e * DMODEL + d];
    }
    __shared__ float red[NE * 8];
    int lane = threadIdx.x & 31, wid = threadIdx.x >> 5;
    #pragma unroll
    for (int e = 0; e < NE; e++) {
        float v = acc[e];
        #pragma unroll
        for (int off = 16; off; off >>= 1) v += __shfl_xor_sync(0xffffffffu, v, off);
        if (lane == 0) red[e * 8 + wid] = v;
    }
    __syncthreads();
    __shared__ float sc_s[NE];
    if (threadIdx.x < NE) {
        float sum = 0.f;
        #pragma unroll
        for (int wq = 0; wq < 8; wq++) sum += red[threadIdx.x * 8 + wq];
        sc_s[threadIdx.x] = 1.f / (1.f + expf(-sum));
    }
    __syncthreads();
    if (threadIdx.x == 0) {
        float sc[NE], s2[NE];
        #pragma unroll
        for (int e = 0; e < NE; e++) { sc[e] = sc_s[e]; s2[e] = sc[e] + gate_bias[e]; }
        float gs[NG];
        #pragma unroll
        for (int gq = 0; gq < NG; gq++) {
            float m1 = -INFINITY, m2 = -INFINITY;
            #pragma unroll
            for (int j = 0; j < NE / NG; j++) {
                float vv = s2[gq * (NE / NG) + j];
                if (vv > m1) { m2 = m1; m1 = vv; }
                else if (vv > m2) { m2 = vv; }
            }
            gs[gq] = m1 + m2;
        }
        bool gsel[NG] = {false, false, false, false};
        {
            float gtmp[NG];
            #pragma unroll
            for (int gq = 0; gq < NG; gq++) gtmp[gq] = gs[gq];
            for (int it = 0; it < NTKG; it++) {
                int bi = 0; float bv = -INFINITY;
                #pragma unroll
                for (int gq = 0; gq < NG; gq++)
                    if (gtmp[gq] > bv) { bv = gtmp[gq]; bi = gq; }
                gsel[bi] = true; gtmp[bi] = -INFINITY;
            }
        }
        float masked[NE];
        #pragma unroll
        for (int e = 0; e < NE; e++) masked[e] = gsel[e >> 2] ? s2[e] : 0.f;
        int inds[NTOPK];
        for (int it = 0; it < NTOPK; it++) {
            int bi = 0; float bv = -INFINITY;
            #pragma unroll
            for (int e = 0; e < NE; e++)
                if (masked[e] > bv) { bv = masked[e]; bi = e; }
            inds[it] = bi; masked[bi] = -INFINITY;
        }
        float wv[NTOPK], wsum = 0.f;
        #pragma unroll
        for (int i = 0; i < NTOPK; i++) { wv[i] = sc[inds[i]]; wsum += wv[i]; }
        float invw = RSF / (wsum + 1e-20f);
        float crow[NE];
        #pragma unroll
        for (int e = 0; e < NE; e++) crow[e] = 0.f;
        #pragma unroll
        for (int i = 0; i < NTOPK; i++) crow[inds[i]] += wv[i] * invw;
        #pragma unroll
        for (int e = 0; e < NE; e++) g_Cw[t * NE + e] = crow[e];
        #pragma unroll
        for (int i = 0; i < NTOPK; i++) {
            int e = inds[i];
            int posn = atomicAdd(&g_cnt[e], 1);
            g_bucket[e * NT + posn] = t;
        }
    }
}

// ---------------- elementwise combines ----------------
__global__ __launch_bounds__(256) void combine_expert_kernel()
{
    long stride = (long)gridDim.x * 256;
    for (int e = 0; e < NE; e++) {
        int cnt = g_cnt[e];
        long work = (long)cnt * EI;
        for (long idx = (long)blockIdx.x * 256 + threadIdx.x; idx < work; idx += stride) {
            int m = (int)(idx / EI);
            int tok = g_bucket[e * NT + m];
            float w = g_Cw[tok * NE + e];
            size_t o = ((size_t)e * NT + m) * EI + (idx % EI);
            float gv = g_eg[o], uv = g_eu[o];
            g_eg[o] = (gv / (1.f + expf(-gv))) * uv * w;
        }
    }
}

__global__ __launch_bounds__(256) void combine_shared_kernel()
{
    size_t idx = (size_t)blockIdx.x * 256 + threadIdx.x;
    if (idx >= (size_t)NT * SHI) return;
    float gv = g_sg[idx], uv = g_su[idx];
    g_sg[idx] = (gv / (1.f + expf(-gv))) * uv;
}

// ---------------- final: out = h1 + y ----------------
__global__ void final_add_kernel(float* __restrict__ out)
{
    int i = blockIdx.x * blockDim.x + threadIdx.x;
    if (i < NT * DMODEL) out[i] = g_h1[i] + g_y[i];
}

// ---------------- launch ----------------
extern "C" void kernel_launch(void* const* d_in, const int* in_sizes, int n_in,
                              void* d_out, int out_size)
{
    const float* x        = (const float*)d_in[0];
    const float* w_q      = (const float*)d_in[1];
    const float* w_k      = (const float*)d_in[2];
    const float* w_v      = (const float*)d_in[3];
    const float* w_o      = (const float*)d_in[4];
    const float* q_norm_w = (const float*)d_in[5];
    const float* k_norm_w = (const float*)d_in[6];
    const float* ln1_w    = (const float*)d_in[7];
    const float* ln2_w    = (const float*)d_in[8];
    const float* gate_w   = (const float*)d_in[9];
    const float* gate_b   = (const float*)d_in[10];
    const float* wg       = (const float*)d_in[11];
    const float* wu       = (const float*)d_in[12];
    const float* wd       = (const float*)d_in[13];
    const float* sh_g     = (const float*)d_in[14];
    const float* sh_u     = (const float*)d_in[15];
    const float* sh_d     = (const float*)d_in[16];
    float* out = (float*)d_out;

    static int attr_done = 0;
    if (!attr_done) {
        cudaFuncSetAttribute(qkv3_kernel,       cudaFuncAttributeMaxDynamicSharedMemorySize, GEMM_SMEM);
        cudaFuncSetAttribute(gemm3o_kernel,     cudaFuncAttributeMaxDynamicSharedMemorySize, GEMM_SMEM);
        cudaFuncSetAttribute(dense1_kernel,     cudaFuncAttributeMaxDynamicSharedMemorySize, GEMM_SMEM);
        cudaFuncSetAttribute(dense1_dual_kernel,cudaFuncAttributeMaxDynamicSharedMemorySize, GEMM_SMEM);
        cudaFuncSetAttribute(egu1_kernel,       cudaFuncAttributeMaxDynamicSharedMemorySize, GEMM_SMEM);
        cudaFuncSetAttribute(edown1_kernel,     cudaFuncAttributeMaxDynamicSharedMemorySize, GEMM_SMEM);
        attr_done = 1;
    }

    float *ph, *ph1, *pt, *psg, *psu, *py;
    cudaGetSymbolAddress((void**)&ph,    g_h);
    cudaGetSymbolAddress((void**)&ph1,   g_h1);
    cudaGetSymbolAddress((void**)&pt,    g_t);
    cudaGetSymbolAddress((void**)&psg,   g_sg);
    cudaGetSymbolAddress((void**)&psu,   g_su);
    cudaGetSymbolAddress((void**)&py,    g_y);

    float* pattn;
    cudaGetSymbolAddress((void**)&pattn, g_attn);

    // 1. RoPE table
    rope_table_kernel<<<LSEQ, 64>>>();
    // 2. pre-attn norm
    rmsnorm_kernel<<<LSEQ, 256>>>(x, ln1_w, ph);
    // 3. fused QKV projection (3xTF32, ldmatrix)
    qkv3_kernel<<<dim3(24, 16), 256, GEMM_SMEM>>>(ph, w_q, w_k, w_v);
    // 4. fused q/k rmsnorm + rope
    qknorm_rope_kernel<<<LSEQ * (NH + NKVH), 128>>>(q_norm_w, k_norm_w);
    // 5. attention (fp32 f32x2)  <- profiled launch
    attn_kernel<<<dim3(LSEQ / 32, NH), 128>>>();
    // 6. output proj + residual (3xTF32, ldmatrix)
    gemm3o_kernel<<<dim3(16, 16), 256, GEMM_SMEM>>>(pattn, w_o, ph1, x);
    // 7. post-attn norm
    rmsnorm_kernel<<<LSEQ, 256>>>(ph1, ln2_w, pt);
    // 8. routing (fp32, exact)
    zero_cnt_kernel<<<1, 32>>>();
    gate_kernel<<<NT, 256>>>(gate_w, gate_b);
    // 9. shared expert: gate+up, combine, down (STORES y)
    dense1_dual_kernel<<<dim3(SHI / 128, NT / 128, 2), 256, GEMM_SMEM>>>(
        pt, sh_g, sh_u, psg, psu, SHI, DMODEL);
    combine_shared_kernel<<<(int)(((size_t)NT * SHI + 255) / 256), 256>>>();
    dense1_kernel<<<dim3(DMODEL / 128, NT / 128), 256, GEMM_SMEM>>>(psg, sh_d, py, DMODEL, SHI);
    // 10. routed experts: gate+up, combine, down (atomicAdd y)
    egu1_kernel<<<dim3(EI / 128, NT / 128, NE * 2), 256, GEMM_SMEM>>>(wg, wu);
    combine_expert_kernel<<<1184, 256>>>();
    edown1_kernel<<<dim3(DMODEL / 128, NT / 128, NE), 256, GEMM_SMEM>>>(wd);
    // 11. final residual add
    final_add_kernel<<<(NT * DMODEL + 255) / 256, 256>>>(out);
    (void)in_sizes; (void)n_in; (void)out_size;
}